// round 1
// baseline (speedup 1.0000x reference)
#include <cuda_runtime.h>
#include <cuda_bf16.h>
#include <math.h>

#define B_ 32
#define L_ 110
#define G_ 512
#define N_ 40
#define D_ 300
#define MAXN_ 110
#define WPF 10
#define EPS_ 1e-8f
#define CLIP_ (1.0f - 1e-6f)
#define BL_ (B_ * L_)          // 3520
#define BLN_ (B_ * L_ * N_)    // 140800

// ---------------- scratch (device globals; no allocs allowed) ----------------
__device__ float g_att_sem[(size_t)BL_ * G_];        // 7.2 MB
__device__ float g_Y[(size_t)BLN_ * D_];             // 169 MB
__device__ float g_nf[BL_];
__device__ float g_na[BL_];
__device__ float g_nY[BLN_];

// ---------------- generic tiled SGEMM: C[M,N] = A[M,K] * B ----------------
// TRANSB=false: B(k,n) = Bm[k*ldb + n];  TRANSB=true: B(k,n) = Bm[n*ldb + k]
template<bool TRANSB>
__global__ __launch_bounds__(256)
void sgemm_kernel(const float* __restrict__ A, const float* __restrict__ Bm,
                  float* __restrict__ C, int M, int N, int K, int ldb)
{
    constexpr int BM = 128, BN = 64, BK = 16, TM = 8, TN = 4;
    __shared__ float As[BK][BM];
    __shared__ float Bs[BK][BN];

    const int tid = threadIdx.x;
    const int tx = tid & 15;        // 0..15  -> 64 cols
    const int ty = tid >> 4;        // 0..15  -> 128 rows
    const int rowBase = blockIdx.x * BM;
    const int colBase = blockIdx.y * BN;

    float acc[TM][TN];
#pragma unroll
    for (int i = 0; i < TM; i++)
#pragma unroll
        for (int j = 0; j < TN; j++) acc[i][j] = 0.f;

    for (int k0 = 0; k0 < K; k0 += BK) {
        // --- load A tile (128 x 16) as float4 along K: 512 vec / 256 thr = 2 each
#pragma unroll
        for (int i = 0; i < 2; i++) {
            int f = tid + i * 256;          // 0..511
            int r = f >> 2;                 // row in tile 0..127
            int c4 = (f & 3) << 2;          // 0,4,8,12
            int grow = rowBase + r;
            int gk = k0 + c4;
            float4 v = make_float4(0.f, 0.f, 0.f, 0.f);
            if (grow < M) {
                if (gk + 3 < K) {
                    v = *reinterpret_cast<const float4*>(&A[(size_t)grow * K + gk]);
                } else {
                    float t0 = (gk + 0 < K) ? A[(size_t)grow * K + gk + 0] : 0.f;
                    float t1 = (gk + 1 < K) ? A[(size_t)grow * K + gk + 1] : 0.f;
                    float t2 = (gk + 2 < K) ? A[(size_t)grow * K + gk + 2] : 0.f;
                    float t3 = (gk + 3 < K) ? A[(size_t)grow * K + gk + 3] : 0.f;
                    v = make_float4(t0, t1, t2, t3);
                }
            }
            As[c4 + 0][r] = v.x; As[c4 + 1][r] = v.y;
            As[c4 + 2][r] = v.z; As[c4 + 3][r] = v.w;
        }
        // --- load B tile (16 x 64): 1024 / 256 = 4 each
#pragma unroll
        for (int i = 0; i < 4; i++) {
            int p = tid + i * 256;
            int kr = p >> 6;                // 0..15
            int nc = p & 63;
            int gk = k0 + kr, gn = colBase + nc;
            float v = 0.f;
            if (gk < K && gn < N)
                v = TRANSB ? Bm[(size_t)gn * ldb + gk] : Bm[(size_t)gk * ldb + gn];
            Bs[kr][nc] = v;
        }
        __syncthreads();

#pragma unroll
        for (int kk = 0; kk < BK; kk++) {
            float a[TM], bb[TN];
            float4 a0 = *reinterpret_cast<const float4*>(&As[kk][ty * TM]);
            float4 a1 = *reinterpret_cast<const float4*>(&As[kk][ty * TM + 4]);
            a[0] = a0.x; a[1] = a0.y; a[2] = a0.z; a[3] = a0.w;
            a[4] = a1.x; a[5] = a1.y; a[6] = a1.z; a[7] = a1.w;
            float4 b0 = *reinterpret_cast<const float4*>(&Bs[kk][tx * TN]);
            bb[0] = b0.x; bb[1] = b0.y; bb[2] = b0.z; bb[3] = b0.w;
#pragma unroll
            for (int i = 0; i < TM; i++)
#pragma unroll
                for (int j = 0; j < TN; j++)
                    acc[i][j] = fmaf(a[i], bb[j], acc[i][j]);
        }
        __syncthreads();
    }

#pragma unroll
    for (int i = 0; i < TM; i++) {
        int grow = rowBase + ty * TM + i;
        if (grow >= M) continue;
        int gcol = colBase + tx * TN;
        if (gcol + TN <= N) {
            *reinterpret_cast<float4*>(&C[(size_t)grow * N + gcol]) =
                make_float4(acc[i][0], acc[i][1], acc[i][2], acc[i][3]);
        } else {
#pragma unroll
            for (int j = 0; j < TN; j++)
                if (gcol + j < N) C[(size_t)grow * N + gcol + j] = acc[i][j];
        }
    }
}

// ---------------- row L2-norm: one warp per row ----------------
__global__ __launch_bounds__(256)
void rownorm_kernel(const float* __restrict__ X, float* __restrict__ out,
                    int rows, int len, int clampEps)
{
    int w = (blockIdx.x * blockDim.x + threadIdx.x) >> 5;
    int lane = threadIdx.x & 31;
    if (w >= rows) return;
    const float* p = X + (size_t)w * len;
    float s = 0.f;
    for (int i = lane; i < len; i += 32) { float v = p[i]; s = fmaf(v, v, s); }
#pragma unroll
    for (int o = 16; o; o >>= 1) s += __shfl_xor_sync(0xffffffffu, s, o);
    if (lane == 0) {
        float nv = sqrtf(s);
        out[w] = clampEps ? fmaxf(nv, EPS_) : nv;
    }
}

// ---------------- fused banded pair / softmax / output kernel ----------------
// grid: B_*L_ blocks (j fastest), 256 threads
__global__ __launch_bounds__(256)
void pair_kernel(const float* __restrict__ node,      // (B,L,G)
                 const float* __restrict__ knowledge, // (B,L,N,D)
                 const float* __restrict__ anew,      // (B,L,N)
                 const int*   __restrict__ tlen,      // (B,)
                 float*       __restrict__ out)       // (B,L,MAXN)
{
    __shared__ float sKj[N_ * D_];   // 48000 B
    __shared__ float s_nKj[N_];
    __shared__ float s_score[24];
    __shared__ float s_con[24];

    const int bj = blockIdx.x;
    const int b = bj / L_;
    const int j = bj % L_;
    const int tid = threadIdx.x;
    const int cur = tlen[b];
    float* outrow = out + (size_t)bj * MAXN_;

    if (j >= cur) {
        for (int k = tid; k < MAXN_; k += 256) outrow[k] = 0.f;
        return;
    }

    // stage K_j tile into shared
    const float* Kj = knowledge + (size_t)bj * N_ * D_;
    for (int i = tid; i < N_ * D_; i += 256) sKj[i] = Kj[i];
    if (tid < 24) { s_con[tid] = 0.f; }
    __syncthreads();

    const int warp = tid >> 5, lane = tid & 31;
    const int k0 = max(0, j - WPF);
    const int k1 = min(min(L_ - 1, j + WPF), cur - 1);
    const int nW = k1 - k0 + 1;     // >= 1 since j < cur

    // per-n norms of K_j (from shared)
    for (int n = warp; n < N_; n += 8) {
        float s = 0.f;
        for (int d = lane; d < D_; d += 32) { float v = sKj[n * D_ + d]; s = fmaf(v, v, s); }
#pragma unroll
        for (int o = 16; o; o >>= 1) s += __shfl_xor_sync(0xffffffffu, s, o);
        if (lane == 0) s_nKj[n] = fmaxf(sqrtf(s), EPS_);
    }

    // semantic scores: warp per window position
    const float nfv = g_nf[bj];
    const float* nfj = node + (size_t)bj * G_;
    for (int w = warp; w < nW; w += 8) {
        int k = k0 + w;
        const float* as = g_att_sem + (size_t)(b * L_ + k) * G_;
        float s = 0.f;
        for (int g = lane; g < G_; g += 32) s = fmaf(nfj[g], as[g], s);
#pragma unroll
        for (int o = 16; o; o >>= 1) s += __shfl_xor_sync(0xffffffffu, s, o);
        if (lane == 0) {
            float c = s / (nfv * g_na[b * L_ + k]);
            c = fminf(fmaxf(c, -CLIP_), CLIP_);
            s_score[w] = 1.0f - acosf(c) * (float)(1.0 / M_PI);
        }
    }
    __syncthreads();

    // contextual part: warp per (k, n) task
    for (int t = warp; t < nW * N_; t += 8) {
        int w = t / N_, n = t - w * N_;
        int k = k0 + w;
        const float* Yk = g_Y + ((size_t)(b * L_ + k) * N_ + n) * D_;
        float s = 0.f;
        for (int d = lane; d < D_; d += 32) s = fmaf(Yk[d], sKj[n * D_ + d], s);
#pragma unroll
        for (int o = 16; o; o >>= 1) s += __shfl_xor_sync(0xffffffffu, s, o);
        if (lane == 0) {
            float a = anew[(size_t)(b * L_ + k) * N_ + n];
            float am = a - 0.5f;
            float aff = (sqrtf(fmaf(am, am, 0.25f * a * a)) - 0.06467f) * (1.0f / 0.607468f);
            float nfc = fmaxf(aff * g_nY[(size_t)(b * L_ + k) * N_ + n], EPS_);
            float cosc = (aff * s) / (nfc * s_nKj[n]);
            atomicAdd(&s_con[w], fabsf(cosc));
        }
    }
    __syncthreads();

    // softmax over the window (single warp; nW <= 21)
    if (warp == 0) {
        float v = (lane < nW) ? s_score[lane] : -3.402823466e38f;
        float m = v;
#pragma unroll
        for (int o = 16; o; o >>= 1) m = fmaxf(m, __shfl_xor_sync(0xffffffffu, m, o));
        float e = (lane < nW) ? expf(v - m) : 0.f;
        float ss = e;
#pragma unroll
        for (int o = 16; o; o >>= 1) ss += __shfl_xor_sync(0xffffffffu, ss, o);
        ss = fmaxf(ss, EPS_);
        if (lane < nW) s_score[lane] = e / ss;   // now alphas_sem
    }
    __syncthreads();

    for (int k = tid; k < MAXN_; k += 256) {
        float v = 0.f;
        if (k >= k0 && k <= k1)
            v = 0.5f * s_score[k - k0] + 5.0f * s_con[k - k0];
        outrow[k] = v;
    }
}

// ---------------- launch ----------------
extern "C" void kernel_launch(void* const* d_in, const int* in_sizes, int n_in,
                              void* d_out, int out_size)
{
    const float* node      = (const float*)d_in[0];
    const float* knowledge = (const float*)d_in[1];
    const float* anew      = (const float*)d_in[2];
    const float* wsem      = (const float*)d_in[3];
    const float* wcon      = (const float*)d_in[4];
    const int*   tlen      = (const int*)d_in[5];
    float* out = (float*)d_out;

    float *attsem, *Yp, *nf, *na, *nY;
    cudaGetSymbolAddress((void**)&attsem, g_att_sem);
    cudaGetSymbolAddress((void**)&Yp,     g_Y);
    cudaGetSymbolAddress((void**)&nf,     g_nf);
    cudaGetSymbolAddress((void**)&na,     g_na);
    cudaGetSymbolAddress((void**)&nY,     g_nY);

    // att_sem[b,l,s] = sum_t node[b,l,t] * Wsem[s,t]  (TRANSB)
    {
        dim3 grid((BL_ + 127) / 128, (G_ + 63) / 64);
        sgemm_kernel<true><<<grid, 256>>>(node, wsem, attsem, BL_, G_, G_, G_);
    }
    // Y[r,t] = sum_s knowledge[r,s] * Wcon[s,t]
    {
        dim3 grid((BLN_ + 127) / 128, (D_ + 63) / 64);
        sgemm_kernel<false><<<grid, 256>>>(knowledge, wcon, Yp, BLN_, D_, D_, D_);
    }
    // norms
    rownorm_kernel<<<(BL_ + 7) / 8, 256>>>(node,   nf, BL_,  G_, 1);
    rownorm_kernel<<<(BL_ + 7) / 8, 256>>>(attsem, na, BL_,  G_, 1);
    rownorm_kernel<<<(BLN_ + 7) / 8, 256>>>(Yp,    nY, BLN_, D_, 0);
    // fused banded attention + output
    pair_kernel<<<BL_, 256>>>(node, knowledge, anew, tlen, out);
}

// round 3
// speedup vs baseline: 1.2593x; 1.2593x over previous
#include <cuda_runtime.h>
#include <cuda_bf16.h>
#include <math.h>
#include <stdint.h>

#define B_ 32
#define L_ 110
#define G_ 512
#define N_ 40
#define D_ 300
#define MAXN_ 110
#define WPF 10
#define EPS_ 1e-8f
#define CLIP_ (1.0f - 1e-6f)
#define BL_ (B_ * L_)          // 3520
#define BLN_ (B_ * L_ * N_)    // 140800

// ---------------- scratch (device globals; no allocs allowed) ----------------
__device__ float g_att_sem[(size_t)BL_ * G_];        // 7.2 MB
__device__ float g_Y[(size_t)BLN_ * D_];             // 169 MB
__device__ float g_WT[320 * 320];                    // padded W_con^T (n x k)
__device__ float g_nf[BL_];
__device__ float g_na[BL_];
__device__ float g_nY[BLN_];

// =================== helpers ===================
__device__ __forceinline__ uint32_t f2tf32(float x) {
    uint32_t r;
    asm("cvt.rna.tf32.f32 %0, %1;" : "=r"(r) : "f"(x));
    return r;
}
__device__ __forceinline__ void mma16n8k8(float* c, const uint32_t* a, const uint32_t* b) {
    asm volatile(
        "mma.sync.aligned.m16n8k8.row.col.f32.tf32.tf32.f32 "
        "{%0,%1,%2,%3}, {%4,%5,%6,%7}, {%8,%9}, {%0,%1,%2,%3};"
        : "+f"(c[0]), "+f"(c[1]), "+f"(c[2]), "+f"(c[3])
        : "r"(a[0]), "r"(a[1]), "r"(a[2]), "r"(a[3]), "r"(b[0]), "r"(b[1]));
}

// =================== TF32 mma.sync GEMM ===================
// C[M x Nc] = A[M x K] * B^T where Bnk is (Nb x K) row-major (B(k,n) = Bnk[n][k]).
// CTA tile 128x64, 8 warps (4 along M, 2 along N), warp tile 32x32.
// K consumed in chunks of 32, double-buffered smem, stride-36 rows.
#define AST 36
#define BST 36
#define SMEM_GEMM_BYTES ((2 * (128 * AST + 64 * BST)) * 4)   // 55296

__global__ __launch_bounds__(256)
void mma_gemm(const float* __restrict__ A, const float* __restrict__ Bnk,
              float* __restrict__ C,
              int M, int Nb, int Nc, int K, int lda, int ldb, int ldc, int NC)
{
    extern __shared__ float sm[];
    float* As = sm;                       // [2][128*AST]
    float* Bs = sm + 2 * 128 * AST;       // [2][64*BST]

    const int tid = threadIdx.x;
    const int warp = tid >> 5, lane = tid & 31;
    const int g = lane >> 2, q = lane & 3;
    const int wm = warp & 3, wn = warp >> 2;
    const int mbase = wm * 32, nbase = wn * 32;
    const size_t m0 = (size_t)blockIdx.x * 128;
    const int n0 = blockIdx.y * 64;

    float acc[2][4][4];
#pragma unroll
    for (int i = 0; i < 2; i++)
#pragma unroll
        for (int j = 0; j < 4; j++)
#pragma unroll
            for (int t = 0; t < 4; t++) acc[i][j][t] = 0.f;

    float4 pa[4], pb[2];

    // ---- load chunk 0 into regs
    {
        const int kb = 0;
#pragma unroll
        for (int i = 0; i < 4; i++) {
            int f = tid + i * 256;
            int r = f >> 3, kv = f & 7;
            int gk = kb + (kv << 2);
            pa[i] = make_float4(0.f, 0.f, 0.f, 0.f);
            if (m0 + r < (size_t)M && gk < K)
                pa[i] = *reinterpret_cast<const float4*>(&A[(m0 + r) * lda + gk]);
        }
#pragma unroll
        for (int i = 0; i < 2; i++) {
            int f = tid + i * 256;
            int r = f >> 3, kv = f & 7;
            int gk = kb + (kv << 2);
            pb[i] = make_float4(0.f, 0.f, 0.f, 0.f);
            if (n0 + r < Nb && gk < K)
                pb[i] = *reinterpret_cast<const float4*>(&Bnk[(size_t)(n0 + r) * ldb + gk]);
        }
    }
    // store chunk 0 to buffer 0
    {
        float* Ab = As;
        float* Bb = Bs;
#pragma unroll
        for (int i = 0; i < 4; i++) {
            int f = tid + i * 256;
            int r = f >> 3, kv = f & 7;
            uint4 u;
            u.x = f2tf32(pa[i].x); u.y = f2tf32(pa[i].y);
            u.z = f2tf32(pa[i].z); u.w = f2tf32(pa[i].w);
            *reinterpret_cast<uint4*>(&Ab[r * AST + (kv << 2)]) = u;
        }
#pragma unroll
        for (int i = 0; i < 2; i++) {
            int f = tid + i * 256;
            int r = f >> 3, kv = f & 7;
            uint4 u;
            u.x = f2tf32(pb[i].x); u.y = f2tf32(pb[i].y);
            u.z = f2tf32(pb[i].z); u.w = f2tf32(pb[i].w);
            *reinterpret_cast<uint4*>(&Bb[r * BST + (kv << 2)]) = u;
        }
    }
    __syncthreads();

    for (int c = 0; c < NC; c++) {
        const int s = c & 1;
        // prefetch next chunk into regs
        if (c + 1 < NC) {
            const int kb = (c + 1) * 32;
#pragma unroll
            for (int i = 0; i < 4; i++) {
                int f = tid + i * 256;
                int r = f >> 3, kv = f & 7;
                int gk = kb + (kv << 2);
                pa[i] = make_float4(0.f, 0.f, 0.f, 0.f);
                if (m0 + r < (size_t)M && gk < K)
                    pa[i] = *reinterpret_cast<const float4*>(&A[(m0 + r) * lda + gk]);
            }
#pragma unroll
            for (int i = 0; i < 2; i++) {
                int f = tid + i * 256;
                int r = f >> 3, kv = f & 7;
                int gk = kb + (kv << 2);
                pb[i] = make_float4(0.f, 0.f, 0.f, 0.f);
                if (n0 + r < Nb && gk < K)
                    pb[i] = *reinterpret_cast<const float4*>(&Bnk[(size_t)(n0 + r) * ldb + gk]);
            }
        }
        // compute on buffer s
        {
            const float* Ab = As + s * 128 * AST;
            const float* Bb = Bs + s * 64 * BST;
#pragma unroll
            for (int ks = 0; ks < 4; ks++) {
                const int k0 = ks * 8;
                uint32_t af[2][4];
#pragma unroll
                for (int mt = 0; mt < 2; mt++) {
                    int base = mbase + mt * 16;
                    af[mt][0] = __float_as_uint(Ab[(base + g) * AST + k0 + q]);
                    af[mt][1] = __float_as_uint(Ab[(base + g + 8) * AST + k0 + q]);
                    af[mt][2] = __float_as_uint(Ab[(base + g) * AST + k0 + q + 4]);
                    af[mt][3] = __float_as_uint(Ab[(base + g + 8) * AST + k0 + q + 4]);
                }
                uint32_t bf[4][2];
#pragma unroll
                for (int nt = 0; nt < 4; nt++) {
                    int bn = nbase + nt * 8 + g;
                    bf[nt][0] = __float_as_uint(Bb[bn * BST + k0 + q]);
                    bf[nt][1] = __float_as_uint(Bb[bn * BST + k0 + q + 4]);
                }
#pragma unroll
                for (int mt = 0; mt < 2; mt++)
#pragma unroll
                    for (int nt = 0; nt < 4; nt++)
                        mma16n8k8(acc[mt][nt], af[mt], bf[nt]);
            }
        }
        __syncthreads();
        if (c + 1 < NC) {
            float* Ab = As + (s ^ 1) * 128 * AST;
            float* Bb = Bs + (s ^ 1) * 64 * BST;
#pragma unroll
            for (int i = 0; i < 4; i++) {
                int f = tid + i * 256;
                int r = f >> 3, kv = f & 7;
                uint4 u;
                u.x = f2tf32(pa[i].x); u.y = f2tf32(pa[i].y);
                u.z = f2tf32(pa[i].z); u.w = f2tf32(pa[i].w);
                *reinterpret_cast<uint4*>(&Ab[r * AST + (kv << 2)]) = u;
            }
#pragma unroll
            for (int i = 0; i < 2; i++) {
                int f = tid + i * 256;
                int r = f >> 3, kv = f & 7;
                uint4 u;
                u.x = f2tf32(pb[i].x); u.y = f2tf32(pb[i].y);
                u.z = f2tf32(pb[i].z); u.w = f2tf32(pb[i].w);
                *reinterpret_cast<uint4*>(&Bb[r * BST + (kv << 2)]) = u;
            }
            __syncthreads();
        }
    }

    // epilogue
#pragma unroll
    for (int mt = 0; mt < 2; mt++) {
        size_t row0 = m0 + mbase + mt * 16 + g;
#pragma unroll
        for (int nt = 0; nt < 4; nt++) {
            int col = n0 + nbase + nt * 8 + q * 2;
            if (row0 < (size_t)M) {
                if (col < Nc)     C[row0 * ldc + col]     = acc[mt][nt][0];
                if (col + 1 < Nc) C[row0 * ldc + col + 1] = acc[mt][nt][1];
            }
            if (row0 + 8 < (size_t)M) {
                if (col < Nc)     C[(row0 + 8) * ldc + col]     = acc[mt][nt][2];
                if (col + 1 < Nc) C[(row0 + 8) * ldc + col + 1] = acc[mt][nt][3];
            }
        }
    }
}

// transpose+pad W_con -> g_WT (n x k layout)
__global__ void wcon_transpose(const float* __restrict__ W, float* __restrict__ WT)
{
    int i = blockIdx.x * 256 + threadIdx.x;
    if (i >= 320 * 320) return;
    int n = i / 320, k = i % 320;
    WT[i] = (n < 300 && k < 300) ? W[k * 300 + n] : 0.f;
}

// ---------------- row L2-norm (float4): one warp per row ----------------
__global__ __launch_bounds__(256)
void rownorm_kernel(const float* __restrict__ X, float* __restrict__ out,
                    int rows, int len4, int clampEps)
{
    int w = (blockIdx.x * blockDim.x + threadIdx.x) >> 5;
    int lane = threadIdx.x & 31;
    if (w >= rows) return;
    const float4* p = reinterpret_cast<const float4*>(X + (size_t)w * (len4 * 4));
    float s = 0.f;
    for (int i = lane; i < len4; i += 32) {
        float4 v = p[i];
        s = fmaf(v.x, v.x, s); s = fmaf(v.y, v.y, s);
        s = fmaf(v.z, v.z, s); s = fmaf(v.w, v.w, s);
    }
#pragma unroll
    for (int o = 16; o; o >>= 1) s += __shfl_xor_sync(0xffffffffu, s, o);
    if (lane == 0) {
        float nv = sqrtf(s);
        out[w] = clampEps ? fmaxf(nv, EPS_) : nv;
    }
}

// ---------------- fused banded pair / softmax / output ----------------
#define D4_ (D_ / 4)   // 75
#define G4_ (G_ / 4)   // 128

__global__ __launch_bounds__(256)
void pair_kernel(const float* __restrict__ node,
                 const float* __restrict__ knowledge,
                 const float* __restrict__ anew,
                 const int*   __restrict__ tlen,
                 float*       __restrict__ out)
{
    __shared__ float4 sKj[N_ * D4_];
    __shared__ float s_nKj[N_];
    __shared__ float s_score[24];
    __shared__ float s_con[24];

    const int bj = blockIdx.x;
    const int b = bj / L_;
    const int j = bj % L_;
    const int tid = threadIdx.x;
    const int cur = tlen[b];
    float* outrow = out + (size_t)bj * MAXN_;

    if (j >= cur) {
        for (int k = tid; k < MAXN_; k += 256) outrow[k] = 0.f;
        return;
    }

    const float4* Kj = reinterpret_cast<const float4*>(knowledge + (size_t)bj * N_ * D_);
    for (int i = tid; i < N_ * D4_; i += 256) sKj[i] = Kj[i];
    if (tid < 24) s_con[tid] = 0.f;
    __syncthreads();

    const int warp = tid >> 5, lane = tid & 31;
    const int k0 = max(0, j - WPF);
    const int k1 = min(min(L_ - 1, j + WPF), cur - 1);
    const int nW = k1 - k0 + 1;

    for (int n = warp; n < N_; n += 8) {
        float s = 0.f;
        for (int i = lane; i < D4_; i += 32) {
            float4 v = sKj[n * D4_ + i];
            s = fmaf(v.x, v.x, s); s = fmaf(v.y, v.y, s);
            s = fmaf(v.z, v.z, s); s = fmaf(v.w, v.w, s);
        }
#pragma unroll
        for (int o = 16; o; o >>= 1) s += __shfl_xor_sync(0xffffffffu, s, o);
        if (lane == 0) s_nKj[n] = fmaxf(sqrtf(s), EPS_);
    }

    const float nfv = g_nf[bj];
    const float4* nfj = reinterpret_cast<const float4*>(node + (size_t)bj * G_);
    for (int w = warp; w < nW; w += 8) {
        int k = k0 + w;
        const float4* as = reinterpret_cast<const float4*>(g_att_sem + (size_t)(b * L_ + k) * G_);
        float s = 0.f;
        for (int i = lane; i < G4_; i += 32) {
            float4 x = nfj[i], y = as[i];
            s = fmaf(x.x, y.x, s); s = fmaf(x.y, y.y, s);
            s = fmaf(x.z, y.z, s); s = fmaf(x.w, y.w, s);
        }
#pragma unroll
        for (int o = 16; o; o >>= 1) s += __shfl_xor_sync(0xffffffffu, s, o);
        if (lane == 0) {
            float c = s / (nfv * g_na[b * L_ + k]);
            c = fminf(fmaxf(c, -CLIP_), CLIP_);
            s_score[w] = 1.0f - acosf(c) * (float)(1.0 / M_PI);
        }
    }
    __syncthreads();

    for (int t = warp; t < nW * N_; t += 8) {
        int w = t / N_, n = t - w * N_;
        int k = k0 + w;
        const float4* Yk = reinterpret_cast<const float4*>(
            g_Y + ((size_t)(b * L_ + k) * N_ + n) * D_);
        float s = 0.f;
        for (int i = lane; i < D4_; i += 32) {
            float4 y = Yk[i], x = sKj[n * D4_ + i];
            s = fmaf(y.x, x.x, s); s = fmaf(y.y, x.y, s);
            s = fmaf(y.z, x.z, s); s = fmaf(y.w, x.w, s);
        }
#pragma unroll
        for (int o = 16; o; o >>= 1) s += __shfl_xor_sync(0xffffffffu, s, o);
        if (lane == 0) {
            float a = anew[(size_t)(b * L_ + k) * N_ + n];
            float am = a - 0.5f;
            float aff = (sqrtf(fmaf(am, am, 0.25f * a * a)) - 0.06467f) * (1.0f / 0.607468f);
            float nfc = fmaxf(aff * g_nY[(size_t)(b * L_ + k) * N_ + n], EPS_);
            float cosc = (aff * s) / (nfc * s_nKj[n]);
            atomicAdd(&s_con[w], fabsf(cosc));
        }
    }
    __syncthreads();

    if (warp == 0) {
        float v = (lane < nW) ? s_score[lane] : -3.402823466e38f;
        float m = v;
#pragma unroll
        for (int o = 16; o; o >>= 1) m = fmaxf(m, __shfl_xor_sync(0xffffffffu, m, o));
        float e = (lane < nW) ? expf(v - m) : 0.f;
        float ss = e;
#pragma unroll
        for (int o = 16; o; o >>= 1) ss += __shfl_xor_sync(0xffffffffu, ss, o);
        ss = fmaxf(ss, EPS_);
        if (lane < nW) s_score[lane] = e / ss;
    }
    __syncthreads();

    for (int k = tid; k < MAXN_; k += 256) {
        float v = 0.f;
        if (k >= k0 && k <= k1)
            v = 0.5f * s_score[k - k0] + 5.0f * s_con[k - k0];
        outrow[k] = v;
    }
}

// ---------------- launch ----------------
extern "C" void kernel_launch(void* const* d_in, const int* in_sizes, int n_in,
                              void* d_out, int out_size)
{
    const float* node      = (const float*)d_in[0];
    const float* knowledge = (const float*)d_in[1];
    const float* anew      = (const float*)d_in[2];
    const float* wsem      = (const float*)d_in[3];
    const float* wcon      = (const float*)d_in[4];
    const int*   tlen      = (const int*)d_in[5];
    float* out = (float*)d_out;

    float *attsem, *Yp, *WTp, *nf, *na, *nY;
    cudaGetSymbolAddress((void**)&attsem, g_att_sem);
    cudaGetSymbolAddress((void**)&Yp,     g_Y);
    cudaGetSymbolAddress((void**)&WTp,    g_WT);
    cudaGetSymbolAddress((void**)&nf,     g_nf);
    cudaGetSymbolAddress((void**)&na,     g_na);
    cudaGetSymbolAddress((void**)&nY,     g_nY);

    static bool attr_set = false;
    if (!attr_set) {
        cudaFuncSetAttribute(mma_gemm, cudaFuncAttributeMaxDynamicSharedMemorySize,
                             SMEM_GEMM_BYTES);
        attr_set = true;
    }

    // pad+transpose W_con -> (n x k)
    wcon_transpose<<<(320 * 320 + 255) / 256, 256>>>(wcon, WTp);

    // att_sem = node @ Wsem^T : A=node (3520x512), Bnk=wsem (512x512 n-by-k)
    {
        dim3 grid((BL_ + 127) / 128, 512 / 64);
        mma_gemm<<<grid, 256, SMEM_GEMM_BYTES>>>(node, wsem, attsem,
                                                 BL_, 512, 512, 512,
                                                 512, 512, 512, 16);
    }
    // Y = knowledge @ Wcon : A=knowledge (140800x300), Bnk=g_WT (320x320)
    {
        dim3 grid(BLN_ / 128, 320 / 64);
        mma_gemm<<<grid, 256, SMEM_GEMM_BYTES>>>(knowledge, WTp, Yp,
                                                 BLN_, 320, 300, 300,
                                                 300, 320, 300, 10);
    }
    // norms
    rownorm_kernel<<<(BL_ + 7) / 8, 256>>>(node,   nf, BL_,  G4_, 1);
    rownorm_kernel<<<(BL_ + 7) / 8, 256>>>(attsem, na, BL_,  G4_, 1);
    rownorm_kernel<<<(BLN_ + 7) / 8, 256>>>(Yp,    nY, BLN_, D4_, 0);
    // fused banded attention + output
    pair_kernel<<<BL_, 256>>>(node, knowledge, anew, tlen, out);
}